// round 12
// baseline (speedup 1.0000x reference)
#include <cuda_runtime.h>
#include <cstdint>

#define B_    8
#define V_    100000
#define FIN_  32
#define K_    4
#define FOUT_ 64
#define E_    800000
#define FH    128                       // floats per vertex per half (32f x 4b, j = f*4+bl)
#define HVF   ((size_t)V_ * FH)         // floats per Chebyshev order per half
#define CSR_B 98                        // csr kernel blocks (98*1024 >= V_)
#define ESMEM ((8192 + 8 * 512 * 4) * 4)   // ws 32KB + xst 64KB

// ---- scratch (static device globals; no allocation) ----
__device__ float d_x[3ull * HVF];       // x0T, x1, x2 for current half (x3 lives in smem)
__device__ int   d_counts[V_];          // zero at load; re-zeroed by csr kernel each run
__device__ int   d_rowptr[V_ + 1];
__device__ int   d_cursor[V_];
__device__ int   d_ccol[E_];
__device__ float d_cval[E_];
__device__ int   d_agg[CSR_B];

// sense-reversing grid-barrier state (self-resetting, replay-deterministic)
__device__ unsigned b_count;
__device__ volatile unsigned b_sense;

// ---------------- packed f32x2 helpers ----------------
__device__ __forceinline__ unsigned long long pack2(float a, float b) {
    unsigned long long r;
    asm("mov.b64 %0, {%1, %2};" : "=l"(r) : "f"(a), "f"(b));
    return r;
}
__device__ __forceinline__ unsigned long long fma2(unsigned long long x,
                                                   unsigned long long y,
                                                   unsigned long long c) {
    unsigned long long r;
    asm("fma.rn.f32x2 %0, %1, %2, %3;" : "=l"(r) : "l"(x), "l"(y), "l"(c));
    return r;
}
__device__ __forceinline__ void unpack2(unsigned long long v, float& lo, float& hi) {
    asm("mov.b64 {%0, %1}, %2;" : "=f"(lo), "=f"(hi) : "l"(v));
}

// sense-reversing grid barrier: count resets each use, sense alternates (relative check)
__device__ __forceinline__ void gbar(int nb) {
    __threadfence();
    __syncthreads();
    if (threadIdx.x == 0) {
        unsigned sense = b_sense;
        if (atomicAdd(&b_count, 1) == (unsigned)(nb - 1)) {
            b_count = 0;
            __threadfence();
            *(unsigned*)&b_sense = sense ^ 1u;
        } else {
            while (b_sense == sense) { }
            __threadfence();
        }
    }
    __syncthreads();
}

// ---------------- 1. CSR build: hist + scan (lookback) + scatter, one kernel ----------
__device__ __forceinline__ int block_exscan(int v, int* total) {
    const int lane = threadIdx.x & 31;
    const int wid = threadIdx.x >> 5;
    int inc = v;
    #pragma unroll
    for (int o = 1; o < 32; o <<= 1) {
        int n = __shfl_up_sync(0xffffffffu, inc, o);
        if (lane >= o) inc += n;
    }
    __shared__ int wsum[32];
    if (lane == 31) wsum[wid] = inc;
    __syncthreads();
    if (wid == 0) {
        int s = wsum[lane];
        #pragma unroll
        for (int o = 1; o < 32; o <<= 1) {
            int n = __shfl_up_sync(0xffffffffu, s, o);
            if (lane >= o) s += n;
        }
        wsum[lane] = s;
    }
    __syncthreads();
    int excl = inc - v + (wid ? wsum[wid - 1] : 0);
    *total = wsum[31];
    return excl;
}

__global__ __launch_bounds__(1024) void csr_kernel(const int* __restrict__ rows,
                                                   const int* __restrict__ cols,
                                                   const float* __restrict__ vals) {
    const int gtid = blockIdx.x * 1024 + threadIdx.x;
    const int stride = CSR_B * 1024;

    // --- hist (d_counts was zeroed by previous call / load) ---
    for (int e = gtid; e < E_; e += stride) atomicAdd(&d_counts[rows[e]], 1);
    gbar(CSR_B);

    // --- scan with decoupled lookback ---
    int c = (gtid < V_) ? d_counts[gtid] : 0;
    int total;
    int excl = block_exscan(c, &total);
    __shared__ int s_off;
    if (threadIdx.x == 0) {
        s_off = 0;
        __threadfence();
        atomicExch(&d_agg[blockIdx.x], total + 1);
    }
    __syncthreads();
    if ((int)threadIdx.x < (int)blockIdx.x) {
        int v;
        do { v = atomicAdd(&d_agg[threadIdx.x], 0); } while (v == 0);
        atomicAdd(&s_off, v - 1);
    }
    __syncthreads();
    const int off = s_off;
    if (gtid < V_) {
        int r = excl + off;
        d_rowptr[gtid] = r;
        d_cursor[gtid] = r;
    }
    if (gtid == 0) d_rowptr[V_] = E_;
    gbar(CSR_B);

    // --- scatter + cleanup for next replay ---
    for (int i = gtid; i < V_; i += stride) d_counts[i] = 0;
    if (gtid < CSR_B) d_agg[gtid] = 0;
    for (int e = gtid; e < E_; e += stride) {
        int r = rows[e];
        int p = atomicAdd(&d_cursor[r], 1);
        d_ccol[p] = cols[e];
        d_cval[p] = vals[e];
    }
}

// ---------------- 2. SpMM pass 1 + transpose (per batch-half) ----------------
__global__ __launch_bounds__(256) void spmm1t_kernel(const float* __restrict__ in, int h) {
    __shared__ float st[8][336];
    const int wrp = threadIdx.x >> 5;
    const int lane = threadIdx.x & 31;
    const int v = blockIdx.x * 8 + wrp;
    const int bl = lane >> 3;
    const int f0 = (lane & 7) * 4;
    const float* base = in + ((size_t)(h * 4 + bl) * V_) * FIN_ + f0;

    const int s = __ldg(&d_rowptr[v]);
    const int e = __ldg(&d_rowptr[v + 1]);

    float4 aA = make_float4(0.f, 0.f, 0.f, 0.f);
    float4 aB = make_float4(0.f, 0.f, 0.f, 0.f);
    int i = s;
    for (; i + 1 < e; i += 2) {
        int   c0 = __ldg(&d_ccol[i]);
        int   c1 = __ldg(&d_ccol[i + 1]);
        float w0 = __ldg(&d_cval[i]);
        float w1 = __ldg(&d_cval[i + 1]);
        float4 u = __ldg(reinterpret_cast<const float4*>(base + (size_t)c0 * FIN_));
        float4 q = __ldg(reinterpret_cast<const float4*>(base + (size_t)c1 * FIN_));
        aA.x = fmaf(w0, u.x, aA.x); aA.y = fmaf(w0, u.y, aA.y);
        aA.z = fmaf(w0, u.z, aA.z); aA.w = fmaf(w0, u.w, aA.w);
        aB.x = fmaf(w1, q.x, aB.x); aB.y = fmaf(w1, q.y, aB.y);
        aB.z = fmaf(w1, q.z, aB.z); aB.w = fmaf(w1, q.w, aB.w);
    }
    if (i < e) {
        int   c0 = __ldg(&d_ccol[i]);
        float w0 = __ldg(&d_cval[i]);
        float4 u = __ldg(reinterpret_cast<const float4*>(base + (size_t)c0 * FIN_));
        aA.x = fmaf(w0, u.x, aA.x); aA.y = fmaf(w0, u.y, aA.y);
        aA.z = fmaf(w0, u.z, aA.z); aA.w = fmaf(w0, u.w, aA.w);
    }
    aA.x += aB.x; aA.y += aB.y; aA.z += aB.z; aA.w += aB.w;

    float4 o0 = __ldg(reinterpret_cast<const float4*>(base + (size_t)v * FIN_));

    float* s1 = st[wrp];
    float* s0 = st[wrp] + 168;
    s1[(f0 + 0) * 5 + bl] = aA.x; s1[(f0 + 1) * 5 + bl] = aA.y;
    s1[(f0 + 2) * 5 + bl] = aA.z; s1[(f0 + 3) * 5 + bl] = aA.w;
    s0[(f0 + 0) * 5 + bl] = o0.x; s0[(f0 + 1) * 5 + bl] = o0.y;
    s0[(f0 + 2) * 5 + bl] = o0.z; s0[(f0 + 3) * 5 + bl] = o0.w;
    __syncwarp();

    float4 r1, r0;
    r1.x = s1[5 * lane + 0]; r1.y = s1[5 * lane + 1];
    r1.z = s1[5 * lane + 2]; r1.w = s1[5 * lane + 3];
    r0.x = s0[5 * lane + 0]; r0.y = s0[5 * lane + 1];
    r0.z = s0[5 * lane + 2]; r0.w = s0[5 * lane + 3];

    float* x0T = d_x;
    float* x1g = d_x + HVF;
    *reinterpret_cast<float4*>(&x1g[(size_t)v * FH + lane * 4]) = r1;
    *reinterpret_cast<float4*>(&x0T[(size_t)v * FH + lane * 4]) = r0;
}

// ---------------- 3. SpMM pass 2 (interleaved layout): x2 = 2*(L x1) - x0 ----------
__global__ __launch_bounds__(256) void spmm2_kernel(const float* __restrict__ x,
                                                    const float* __restrict__ z,
                                                    float* __restrict__ y) {
    const int wrp = threadIdx.x >> 5;
    const int lane = threadIdx.x & 31;
    const int v = blockIdx.x * 8 + wrp;
    const int p = lane * 4;
    const int s = __ldg(&d_rowptr[v]);
    const int e = __ldg(&d_rowptr[v + 1]);

    float4 a0 = make_float4(0.f, 0.f, 0.f, 0.f);
    float4 a1 = make_float4(0.f, 0.f, 0.f, 0.f);
    int i = s;
    for (; i + 1 < e; i += 2) {
        int   c0 = __ldg(&d_ccol[i]);
        int   c1 = __ldg(&d_ccol[i + 1]);
        float w0 = __ldg(&d_cval[i]);
        float w1 = __ldg(&d_cval[i + 1]);
        float4 u = __ldg(reinterpret_cast<const float4*>(&x[(size_t)c0 * FH + p]));
        float4 q = __ldg(reinterpret_cast<const float4*>(&x[(size_t)c1 * FH + p]));
        a0.x = fmaf(w0, u.x, a0.x); a0.y = fmaf(w0, u.y, a0.y);
        a0.z = fmaf(w0, u.z, a0.z); a0.w = fmaf(w0, u.w, a0.w);
        a1.x = fmaf(w1, q.x, a1.x); a1.y = fmaf(w1, q.y, a1.y);
        a1.z = fmaf(w1, q.z, a1.z); a1.w = fmaf(w1, q.w, a1.w);
    }
    if (i < e) {
        int   c0 = __ldg(&d_ccol[i]);
        float w0 = __ldg(&d_cval[i]);
        float4 u = __ldg(reinterpret_cast<const float4*>(&x[(size_t)c0 * FH + p]));
        a0.x = fmaf(w0, u.x, a0.x); a0.y = fmaf(w0, u.y, a0.y);
        a0.z = fmaf(w0, u.z, a0.z); a0.w = fmaf(w0, u.w, a0.w);
    }
    float4 zv = __ldg(reinterpret_cast<const float4*>(&z[(size_t)v * FH + p]));
    float4 r;
    r.x = 2.f * (a0.x + a1.x) - zv.x;
    r.y = 2.f * (a0.y + a1.y) - zv.y;
    r.z = 2.f * (a0.z + a1.z) - zv.z;
    r.w = 2.f * (a0.w + a1.w) - zv.w;
    *reinterpret_cast<float4*>(&y[(size_t)v * FH + p]) = r;
}

// ---------------- 4. FUSED einsum: phase A computes x3 in-smem, phase B einsum --------
// Warp owns 4 vertices. Phase A (warp-private, no block sync): gather x2 rows,
// x3 = 2*L*x2 - x1 written straight into the warp's smem slice, stage x0/x1/x2.
// Phase B: thread owns o=lane & o=lane+32; x as broadcast LDS.128, weights LDS.32.
__global__ __launch_bounds__(256) void einsum_fused_kernel(const float* __restrict__ w,
                                                           const float* __restrict__ bias,
                                                           float* __restrict__ out, int h) {
    extern __shared__ __align__(16) float sm[];
    float*  ws  = sm;                                   // 8192 floats (32KB)
    float4* xst = reinterpret_cast<float4*>(sm + 8192); // 8 warps * 512 float4 (64KB)

    const int t = threadIdx.x;
    #pragma unroll
    for (int i = 0; i < 32; i++) ws[i * 256 + t] = w[i * 256 + t];
    __syncthreads();

    const int wrp = t >> 5;
    const int lane = t & 31;
    const int v0 = blockIdx.x * 32 + wrp * 4;           // 3125 blocks * 32 v = V_
    const int p = lane * 4;
    float4* xw = xst + wrp * 512;                       // layout [j][k][f4]

    const float* x0T = d_x;
    const float* x1g = d_x + HVF;
    const float* x2g = d_x + 2 * HVF;

    // ---- Phase A: per-vertex gather + recurrence + staging (warp-private) ----
    #pragma unroll
    for (int j = 0; j < 4; j++) {
        const int v = v0 + j;
        const int s = __ldg(&d_rowptr[v]);
        const int e = __ldg(&d_rowptr[v + 1]);
        float4 a0 = make_float4(0.f, 0.f, 0.f, 0.f);
        float4 a1 = make_float4(0.f, 0.f, 0.f, 0.f);
        int i = s;
        for (; i + 1 < e; i += 2) {
            int   c0 = __ldg(&d_ccol[i]);
            int   c1 = __ldg(&d_ccol[i + 1]);
            float w0 = __ldg(&d_cval[i]);
            float w1 = __ldg(&d_cval[i + 1]);
            float4 u = __ldg(reinterpret_cast<const float4*>(&x2g[(size_t)c0 * FH + p]));
            float4 q = __ldg(reinterpret_cast<const float4*>(&x2g[(size_t)c1 * FH + p]));
            a0.x = fmaf(w0, u.x, a0.x); a0.y = fmaf(w0, u.y, a0.y);
            a0.z = fmaf(w0, u.z, a0.z); a0.w = fmaf(w0, u.w, a0.w);
            a1.x = fmaf(w1, q.x, a1.x); a1.y = fmaf(w1, q.y, a1.y);
            a1.z = fmaf(w1, q.z, a1.z); a1.w = fmaf(w1, q.w, a1.w);
        }
        if (i < e) {
            int   c0 = __ldg(&d_ccol[i]);
            float w0 = __ldg(&d_cval[i]);
            float4 u = __ldg(reinterpret_cast<const float4*>(&x2g[(size_t)c0 * FH + p]));
            a0.x = fmaf(w0, u.x, a0.x); a0.y = fmaf(w0, u.y, a0.y);
            a0.z = fmaf(w0, u.z, a0.z); a0.w = fmaf(w0, u.w, a0.w);
        }
        float4 x1v = __ldg(reinterpret_cast<const float4*>(&x1g[(size_t)v * FH + p]));
        float4 x3v;
        x3v.x = 2.f * (a0.x + a1.x) - x1v.x;
        x3v.y = 2.f * (a0.y + a1.y) - x1v.y;
        x3v.z = 2.f * (a0.z + a1.z) - x1v.z;
        x3v.w = 2.f * (a0.w + a1.w) - x1v.w;

        xw[j * 128 + 0 * 32 + lane] =
            __ldg(reinterpret_cast<const float4*>(&x0T[(size_t)v * FH + p]));
        xw[j * 128 + 1 * 32 + lane] = x1v;
        xw[j * 128 + 2 * 32 + lane] =
            __ldg(reinterpret_cast<const float4*>(&x2g[(size_t)v * FH + p]));
        xw[j * 128 + 3 * 32 + lane] = x3v;
    }
    __syncwarp();

    // ---- Phase B: einsum ----
    const float bo0 = __ldg(&bias[lane]);
    const float bo1 = __ldg(&bias[lane + 32]);

    unsigned long long a[4][2][2];                      // [vertex j][o-slot][batch pair]
    #pragma unroll
    for (int j = 0; j < 4; j++)
        #pragma unroll
        for (int s2 = 0; s2 < 2; s2++) { a[j][s2][0] = 0ull; a[j][s2][1] = 0ull; }

    #pragma unroll 2
    for (int f = 0; f < FIN_; f++) {
        #pragma unroll
        for (int k = 0; k < K_; k++) {
            float w0 = ws[f * 256 + k * 64 + lane];
            float w1 = ws[f * 256 + k * 64 + 32 + lane];
            unsigned long long wp0 = pack2(w0, w0);
            unsigned long long wp1 = pack2(w1, w1);
            #pragma unroll
            for (int j = 0; j < 4; j++) {
                ulonglong2 xv = *reinterpret_cast<const ulonglong2*>(
                    &xw[j * 128 + k * 32 + f]);         // broadcast LDS.128
                a[j][0][0] = fma2(xv.x, wp0, a[j][0][0]);
                a[j][0][1] = fma2(xv.y, wp0, a[j][0][1]);
                a[j][1][0] = fma2(xv.x, wp1, a[j][1][0]);
                a[j][1][1] = fma2(xv.y, wp1, a[j][1][1]);
            }
        }
    }

    #pragma unroll
    for (int j = 0; j < 4; j++) {
        const int v = v0 + j;
        #pragma unroll
        for (int s2 = 0; s2 < 2; s2++) {
            float b0, b1, b2, b3;
            unpack2(a[j][s2][0], b0, b1);
            unpack2(a[j][s2][1], b2, b3);
            const int o = lane + s2 * 32;
            const float bb = s2 ? bo1 : bo0;
            out[((size_t)(h * 4 + 0) * V_ + v) * FOUT_ + o] = b0 + bb;
            out[((size_t)(h * 4 + 1) * V_ + v) * FOUT_ + o] = b1 + bb;
            out[((size_t)(h * 4 + 2) * V_ + v) * FOUT_ + o] = b2 + bb;
            out[((size_t)(h * 4 + 3) * V_ + v) * FOUT_ + o] = b3 + bb;
        }
    }
}

// ---------------- launch ----------------
extern "C" void kernel_launch(void* const* d_in, const int* in_sizes, int n_in,
                              void* d_out, int out_size) {
    const float* inputs = (const float*)d_in[0];
    const int*   rows   = (const int*)d_in[1];
    const int*   cols   = (const int*)d_in[2];
    const float* vals   = (const float*)d_in[3];
    const float* weight = (const float*)d_in[4];
    const float* bias   = (const float*)d_in[5];
    float* out = (float*)d_out;

    float* xbase;
    cudaGetSymbolAddress((void**)&xbase, d_x);

    static bool attr_set = false;
    if (!attr_set) {
        cudaFuncSetAttribute(einsum_fused_kernel,
                             cudaFuncAttributeMaxDynamicSharedMemorySize, ESMEM);
        attr_set = true;
    }

    csr_kernel<<<CSR_B, 1024>>>(rows, cols, vals);                  // 1

    float* x0T = xbase;
    float* x1 = xbase + HVF;
    float* x2 = xbase + 2 * HVF;

    for (int h = 0; h < 2; h++) {
        spmm1t_kernel<<<V_ / 8, 256>>>(inputs, h);                  // 2 / 5
        spmm2_kernel<<<V_ / 8, 256>>>(x1, x0T, x2);                 // 3 / 6
        einsum_fused_kernel<<<V_ / 32, 256, ESMEM>>>(weight, bias, out, h); // 4 (sampled) / 7
    }
}

// round 13
// speedup vs baseline: 1.1667x; 1.1667x over previous
#include <cuda_runtime.h>
#include <cstdint>

#define B_    8
#define V_    100000
#define FIN_  32
#define K_    4
#define FOUT_ 64
#define E_    800000
#define FH    128                       // floats per vertex per half (32f x 4b, j = f*4+bl)
#define HVF   ((size_t)V_ * FH)         // floats per Chebyshev order per half
#define SCAN_B 98                       // scan blocks (98*1024 >= V_)
#define ESMEM ((8192 + 8 * 512 * 4) * 4)   // ws 32KB + xst 64KB

// ---- scratch (static device globals; no allocation) ----
__device__ float d_x[8ull * HVF];       // 2 halves x {x0T, x1, x2, x3}
__device__ int   d_counts[V_];          // zero at load; re-zeroed by scanscatter each run
__device__ int   d_rowptr[V_ + 1];
__device__ int   d_cursor[V_];
__device__ int   d_ccol[E_];
__device__ float d_cval[E_];
__device__ int   d_agg[SCAN_B];

// barrier state for scanscatter (reset by hist_kernel every replay)
__device__ unsigned s_count;
__device__ volatile unsigned s_phase;

// ---------------- packed f32x2 helpers ----------------
__device__ __forceinline__ unsigned long long pack2(float a, float b) {
    unsigned long long r;
    asm("mov.b64 %0, {%1, %2};" : "=l"(r) : "f"(a), "f"(b));
    return r;
}
__device__ __forceinline__ unsigned long long fma2(unsigned long long x,
                                                   unsigned long long y,
                                                   unsigned long long c) {
    unsigned long long r;
    asm("fma.rn.f32x2 %0, %1, %2, %3;" : "=l"(r) : "l"(x), "l"(y), "l"(c));
    return r;
}
__device__ __forceinline__ void unpack2(unsigned long long v, float& lo, float& hi) {
    asm("mov.b64 {%0, %1}, %2;" : "=f"(lo), "=f"(hi) : "l"(v));
}

// ---------------- 1. hist (+ barrier-state reset) ----------------
__global__ void hist_kernel(const int* __restrict__ rows) {
    if (blockIdx.x == 0 && threadIdx.x == 0) {
        s_count = 0; *(unsigned*)&s_phase = 0;
    }
    int e = blockIdx.x * blockDim.x + threadIdx.x;
    if (e < E_) atomicAdd(&d_counts[rows[e]], 1);
}

// ---------------- 2. scan (lookback) + grid barrier + scatter ----------------
__device__ __forceinline__ int block_exscan(int v, int* total) {
    const int lane = threadIdx.x & 31;
    const int wid = threadIdx.x >> 5;
    int inc = v;
    #pragma unroll
    for (int o = 1; o < 32; o <<= 1) {
        int n = __shfl_up_sync(0xffffffffu, inc, o);
        if (lane >= o) inc += n;
    }
    __shared__ int wsum[32];
    if (lane == 31) wsum[wid] = inc;
    __syncthreads();
    if (wid == 0) {
        int s = wsum[lane];
        #pragma unroll
        for (int o = 1; o < 32; o <<= 1) {
            int n = __shfl_up_sync(0xffffffffu, s, o);
            if (lane >= o) s += n;
        }
        wsum[lane] = s;
    }
    __syncthreads();
    int excl = inc - v + (wid ? wsum[wid - 1] : 0);
    *total = wsum[31];
    return excl;
}

__global__ __launch_bounds__(1024) void scanscatter_kernel(const int* __restrict__ rows,
                                                           const int* __restrict__ cols,
                                                           const float* __restrict__ vals) {
    const int gtid = blockIdx.x * 1024 + threadIdx.x;
    int c = (gtid < V_) ? d_counts[gtid] : 0;
    int total;
    int excl = block_exscan(c, &total);
    __shared__ int s_off;
    if (threadIdx.x == 0) {
        s_off = 0;
        __threadfence();
        atomicExch(&d_agg[blockIdx.x], total + 1);
    }
    __syncthreads();
    if ((int)threadIdx.x < (int)blockIdx.x) {
        int v;
        do { v = atomicAdd(&d_agg[threadIdx.x], 0); } while (v == 0);
        atomicAdd(&s_off, v - 1);
    }
    __syncthreads();
    const int off = s_off;
    if (gtid < V_) {
        int r = excl + off;
        d_rowptr[gtid] = r;
        d_cursor[gtid] = r;
    }
    if (gtid == 0) d_rowptr[V_] = E_;

    // grid barrier: rowptr/cursor visible everywhere before scatter
    __threadfence();
    __syncthreads();
    if (threadIdx.x == 0) {
        unsigned t = atomicAdd(&s_count, 1);
        if (t == SCAN_B - 1) {
            s_count = 0;
            __threadfence();
            *(unsigned*)&s_phase = 1;
        } else {
            while (s_phase < 1) { }
            __threadfence();
        }
    }
    __syncthreads();

    const int stride = SCAN_B * 1024;
    for (int i = gtid; i < V_; i += stride) d_counts[i] = 0;
    if (gtid < SCAN_B) d_agg[gtid] = 0;
    for (int e = gtid; e < E_; e += stride) {
        int r = rows[e];
        int p = atomicAdd(&d_cursor[r], 1);
        d_ccol[p] = cols[e];
        d_cval[p] = vals[e];
    }
}

// ---------------- 3. SpMM pass 1 + transpose (per batch-half) ----------------
__global__ __launch_bounds__(256) void spmm1t_kernel(const float* __restrict__ in, int h,
                                                     float* __restrict__ x0T,
                                                     float* __restrict__ x1g) {
    __shared__ float st[8][336];
    const int wrp = threadIdx.x >> 5;
    const int lane = threadIdx.x & 31;
    const int v = blockIdx.x * 8 + wrp;
    const int bl = lane >> 3;
    const int f0 = (lane & 7) * 4;
    const float* base = in + ((size_t)(h * 4 + bl) * V_) * FIN_ + f0;

    const int s = __ldg(&d_rowptr[v]);
    const int e = __ldg(&d_rowptr[v + 1]);

    float4 aA = make_float4(0.f, 0.f, 0.f, 0.f);
    float4 aB = make_float4(0.f, 0.f, 0.f, 0.f);
    int i = s;
    for (; i + 1 < e; i += 2) {
        int   c0 = __ldg(&d_ccol[i]);
        int   c1 = __ldg(&d_ccol[i + 1]);
        float w0 = __ldg(&d_cval[i]);
        float w1 = __ldg(&d_cval[i + 1]);
        float4 u = __ldg(reinterpret_cast<const float4*>(base + (size_t)c0 * FIN_));
        float4 q = __ldg(reinterpret_cast<const float4*>(base + (size_t)c1 * FIN_));
        aA.x = fmaf(w0, u.x, aA.x); aA.y = fmaf(w0, u.y, aA.y);
        aA.z = fmaf(w0, u.z, aA.z); aA.w = fmaf(w0, u.w, aA.w);
        aB.x = fmaf(w1, q.x, aB.x); aB.y = fmaf(w1, q.y, aB.y);
        aB.z = fmaf(w1, q.z, aB.z); aB.w = fmaf(w1, q.w, aB.w);
    }
    if (i < e) {
        int   c0 = __ldg(&d_ccol[i]);
        float w0 = __ldg(&d_cval[i]);
        float4 u = __ldg(reinterpret_cast<const float4*>(base + (size_t)c0 * FIN_));
        aA.x = fmaf(w0, u.x, aA.x); aA.y = fmaf(w0, u.y, aA.y);
        aA.z = fmaf(w0, u.z, aA.z); aA.w = fmaf(w0, u.w, aA.w);
    }
    aA.x += aB.x; aA.y += aB.y; aA.z += aB.z; aA.w += aB.w;

    float4 o0 = __ldg(reinterpret_cast<const float4*>(base + (size_t)v * FIN_));

    float* s1 = st[wrp];
    float* s0 = st[wrp] + 168;
    s1[(f0 + 0) * 5 + bl] = aA.x; s1[(f0 + 1) * 5 + bl] = aA.y;
    s1[(f0 + 2) * 5 + bl] = aA.z; s1[(f0 + 3) * 5 + bl] = aA.w;
    s0[(f0 + 0) * 5 + bl] = o0.x; s0[(f0 + 1) * 5 + bl] = o0.y;
    s0[(f0 + 2) * 5 + bl] = o0.z; s0[(f0 + 3) * 5 + bl] = o0.w;
    __syncwarp();

    float4 r1, r0;
    r1.x = s1[5 * lane + 0]; r1.y = s1[5 * lane + 1];
    r1.z = s1[5 * lane + 2]; r1.w = s1[5 * lane + 3];
    r0.x = s0[5 * lane + 0]; r0.y = s0[5 * lane + 1];
    r0.z = s0[5 * lane + 2]; r0.w = s0[5 * lane + 3];

    *reinterpret_cast<float4*>(&x1g[(size_t)v * FH + lane * 4]) = r1;
    *reinterpret_cast<float4*>(&x0T[(size_t)v * FH + lane * 4]) = r0;
}

// ---------------- 4. SpMM passes 2/3 (interleaved layout): y = 2*(L x) - z ----------
__global__ __launch_bounds__(256) void spmm2_kernel(const float* __restrict__ x,
                                                    const float* __restrict__ z,
                                                    float* __restrict__ y) {
    const int wrp = threadIdx.x >> 5;
    const int lane = threadIdx.x & 31;
    const int v = blockIdx.x * 8 + wrp;
    const int p = lane * 4;
    const int s = __ldg(&d_rowptr[v]);
    const int e = __ldg(&d_rowptr[v + 1]);

    float4 a0 = make_float4(0.f, 0.f, 0.f, 0.f);
    float4 a1 = make_float4(0.f, 0.f, 0.f, 0.f);
    int i = s;
    for (; i + 1 < e; i += 2) {
        int   c0 = __ldg(&d_ccol[i]);
        int   c1 = __ldg(&d_ccol[i + 1]);
        float w0 = __ldg(&d_cval[i]);
        float w1 = __ldg(&d_cval[i + 1]);
        float4 u = __ldg(reinterpret_cast<const float4*>(&x[(size_t)c0 * FH + p]));
        float4 q = __ldg(reinterpret_cast<const float4*>(&x[(size_t)c1 * FH + p]));
        a0.x = fmaf(w0, u.x, a0.x); a0.y = fmaf(w0, u.y, a0.y);
        a0.z = fmaf(w0, u.z, a0.z); a0.w = fmaf(w0, u.w, a0.w);
        a1.x = fmaf(w1, q.x, a1.x); a1.y = fmaf(w1, q.y, a1.y);
        a1.z = fmaf(w1, q.z, a1.z); a1.w = fmaf(w1, q.w, a1.w);
    }
    if (i < e) {
        int   c0 = __ldg(&d_ccol[i]);
        float w0 = __ldg(&d_cval[i]);
        float4 u = __ldg(reinterpret_cast<const float4*>(&x[(size_t)c0 * FH + p]));
        a0.x = fmaf(w0, u.x, a0.x); a0.y = fmaf(w0, u.y, a0.y);
        a0.z = fmaf(w0, u.z, a0.z); a0.w = fmaf(w0, u.w, a0.w);
    }
    float4 zv = __ldg(reinterpret_cast<const float4*>(&z[(size_t)v * FH + p]));
    float4 r;
    r.x = 2.f * (a0.x + a1.x) - zv.x;
    r.y = 2.f * (a0.y + a1.y) - zv.y;
    r.z = 2.f * (a0.z + a1.z) - zv.z;
    r.w = 2.f * (a0.w + a1.w) - zv.w;
    *reinterpret_cast<float4*>(&y[(size_t)v * FH + p]) = r;
}

// ---------------- 5. einsum: warp owns 4 vertices; per-warp smem staging ----------
__global__ __launch_bounds__(256) void einsum_kernel(const float* __restrict__ w,
                                                     const float* __restrict__ bias,
                                                     float* __restrict__ out, int h,
                                                     const float* __restrict__ xb4) {
    extern __shared__ __align__(16) float sm[];
    float*  ws  = sm;                                  // 8192 floats (32KB)
    float4* xst = reinterpret_cast<float4*>(sm + 8192); // 8 warps * 512 float4 (64KB)

    const int t = threadIdx.x;
    #pragma unroll
    for (int i = 0; i < 32; i++) ws[i * 256 + t] = w[i * 256 + t];
    __syncthreads();

    const int wrp = t >> 5;
    const int lane = t & 31;
    const int v0 = blockIdx.x * 32 + wrp * 4;          // 3125 blocks * 32 v = V_
    float4* xw = xst + wrp * 512;                      // this warp's staging slice

    // stage 4 vertices x 4 orders x 32 float4  (layout: [j][k][q], q = f)
    #pragma unroll
    for (int i = 0; i < 16; i++) {
        int idx = i * 32 + lane;                       // 0..511
        int j = idx >> 7;
        int k = (idx >> 5) & 3;
        int q = idx & 31;
        xw[idx] = __ldg(reinterpret_cast<const float4*>(
            xb4 + (size_t)k * HVF + (size_t)(v0 + j) * FH + q * 4));
    }
    __syncwarp();

    const float bo0 = __ldg(&bias[lane]);
    const float bo1 = __ldg(&bias[lane + 32]);

    unsigned long long a[4][2][2];                     // [vertex j][o-slot][batch pair]
    #pragma unroll
    for (int j = 0; j < 4; j++)
        #pragma unroll
        for (int s2 = 0; s2 < 2; s2++) { a[j][s2][0] = 0ull; a[j][s2][1] = 0ull; }

    #pragma unroll 2
    for (int f = 0; f < FIN_; f++) {
        #pragma unroll
        for (int k = 0; k < K_; k++) {
            float w0 = ws[f * 256 + k * 64 + lane];
            float w1 = ws[f * 256 + k * 64 + 32 + lane];
            unsigned long long wp0 = pack2(w0, w0);
            unsigned long long wp1 = pack2(w1, w1);
            #pragma unroll
            for (int j = 0; j < 4; j++) {
                ulonglong2 xv = *reinterpret_cast<const ulonglong2*>(
                    &xw[j * 128 + k * 32 + f]);        // broadcast LDS.128
                a[j][0][0] = fma2(xv.x, wp0, a[j][0][0]);
                a[j][0][1] = fma2(xv.y, wp0, a[j][0][1]);
                a[j][1][0] = fma2(xv.x, wp1, a[j][1][0]);
                a[j][1][1] = fma2(xv.y, wp1, a[j][1][1]);
            }
        }
    }

    #pragma unroll
    for (int j = 0; j < 4; j++) {
        const int v = v0 + j;
        #pragma unroll
        for (int s2 = 0; s2 < 2; s2++) {
            float b0, b1, b2, b3;
            unpack2(a[j][s2][0], b0, b1);
            unpack2(a[j][s2][1], b2, b3);
            const int o = lane + s2 * 32;
            const float bb = s2 ? bo1 : bo0;
            out[((size_t)(h * 4 + 0) * V_ + v) * FOUT_ + o] = b0 + bb;
            out[((size_t)(h * 4 + 1) * V_ + v) * FOUT_ + o] = b1 + bb;
            out[((size_t)(h * 4 + 2) * V_ + v) * FOUT_ + o] = b2 + bb;
            out[((size_t)(h * 4 + 3) * V_ + v) * FOUT_ + o] = b3 + bb;
        }
    }
}

// ---------------- launch ----------------
extern "C" void kernel_launch(void* const* d_in, const int* in_sizes, int n_in,
                              void* d_out, int out_size) {
    const float* inputs = (const float*)d_in[0];
    const int*   rows   = (const int*)d_in[1];
    const int*   cols   = (const int*)d_in[2];
    const float* vals   = (const float*)d_in[3];
    const float* weight = (const float*)d_in[4];
    const float* bias   = (const float*)d_in[5];
    float* out = (float*)d_out;

    float* xbase;
    cudaGetSymbolAddress((void**)&xbase, d_x);

    // one-time config (first call is the uncaptured correctness run)
    static cudaStream_t s2 = nullptr;
    static cudaEvent_t evF = nullptr, evJ = nullptr;
    if (s2 == nullptr) {
        cudaFuncSetAttribute(einsum_kernel,
                             cudaFuncAttributeMaxDynamicSharedMemorySize, ESMEM);
        cudaStreamCreateWithFlags(&s2, cudaStreamNonBlocking);
        cudaEventCreateWithFlags(&evF, cudaEventDisableTiming);
        cudaEventCreateWithFlags(&evJ, cudaEventDisableTiming);
    }

    hist_kernel<<<(E_ + 255) / 256, 256>>>(rows);                   // default stream
    scanscatter_kernel<<<SCAN_B, 1024>>>(rows, cols, vals);         // default stream

    // fork: chain h=1 runs on s2, concurrent with chain h=0 on the default stream
    cudaEventRecord(evF, 0);
    cudaStreamWaitEvent(s2, evF, 0);

    for (int h = 0; h < 2; h++) {
        cudaStream_t st = (h == 0) ? (cudaStream_t)0 : s2;
        float* x0T = xbase + (size_t)h * 4 * HVF;
        float* x1  = x0T + HVF;
        float* x2  = x0T + 2 * HVF;
        float* x3  = x0T + 3 * HVF;
        spmm1t_kernel<<<V_ / 8, 256, 0, st>>>(inputs, h, x0T, x1);
        spmm2_kernel<<<V_ / 8, 256, 0, st>>>(x1, x0T, x2);
        spmm2_kernel<<<V_ / 8, 256, 0, st>>>(x2, x1, x3);
        einsum_kernel<<<V_ / 32, 256, ESMEM, st>>>(weight, bias, out, h, x0T);
    }

    // join: default stream waits for chain h=1
    cudaEventRecord(evJ, s2);
    cudaStreamWaitEvent((cudaStream_t)0, evJ, 0);
}

// round 14
// speedup vs baseline: 1.1707x; 1.0035x over previous
#include <cuda_runtime.h>
#include <cstdint>

#define B_    8
#define V_    100000
#define FIN_  32
#define K_    4
#define FOUT_ 64
#define E_    800000
#define FH    128                       // floats per vertex per half (32f x 4b, j = f*4+bl)
#define HVF   ((size_t)V_ * FH)         // floats per Chebyshev order per half
#define SCAN_B 98                       // scan blocks (98*1024 >= V_)
#define ESMEM (8192 * 4 + 8 * 128 * 16) // ws 32KB + xst 16KB = 48KB -> 4 blocks/SM

// ---- scratch (static device globals; no allocation) ----
__device__ float d_x[8ull * HVF];       // 2 halves x {x0T, x1, x2, x3}
__device__ int   d_counts[V_];          // zero at load; re-zeroed by scanscatter each run
__device__ int   d_rowptr[V_ + 1];
__device__ int   d_cursor[V_];
__device__ int   d_ccol[E_];
__device__ float d_cval[E_];
__device__ int   d_agg[SCAN_B];

// barrier state for scanscatter (reset by hist_kernel every replay)
__device__ unsigned s_count;
__device__ volatile unsigned s_phase;

// ---------------- packed f32x2 helpers ----------------
__device__ __forceinline__ unsigned long long pack2(float a, float b) {
    unsigned long long r;
    asm("mov.b64 %0, {%1, %2};" : "=l"(r) : "f"(a), "f"(b));
    return r;
}
__device__ __forceinline__ unsigned long long fma2(unsigned long long x,
                                                   unsigned long long y,
                                                   unsigned long long c) {
    unsigned long long r;
    asm("fma.rn.f32x2 %0, %1, %2, %3;" : "=l"(r) : "l"(x), "l"(y), "l"(c));
    return r;
}
__device__ __forceinline__ void unpack2(unsigned long long v, float& lo, float& hi) {
    asm("mov.b64 {%0, %1}, %2;" : "=f"(lo), "=f"(hi) : "l"(v));
}

// ---------------- 1. hist (+ barrier-state reset) ----------------
__global__ void hist_kernel(const int* __restrict__ rows) {
    if (blockIdx.x == 0 && threadIdx.x == 0) {
        s_count = 0; *(unsigned*)&s_phase = 0;
    }
    int e = blockIdx.x * blockDim.x + threadIdx.x;
    if (e < E_) atomicAdd(&d_counts[rows[e]], 1);
}

// ---------------- 2. scan (lookback) + grid barrier + scatter ----------------
__device__ __forceinline__ int block_exscan(int v, int* total) {
    const int lane = threadIdx.x & 31;
    const int wid = threadIdx.x >> 5;
    int inc = v;
    #pragma unroll
    for (int o = 1; o < 32; o <<= 1) {
        int n = __shfl_up_sync(0xffffffffu, inc, o);
        if (lane >= o) inc += n;
    }
    __shared__ int wsum[32];
    if (lane == 31) wsum[wid] = inc;
    __syncthreads();
    if (wid == 0) {
        int s = wsum[lane];
        #pragma unroll
        for (int o = 1; o < 32; o <<= 1) {
            int n = __shfl_up_sync(0xffffffffu, s, o);
            if (lane >= o) s += n;
        }
        wsum[lane] = s;
    }
    __syncthreads();
    int excl = inc - v + (wid ? wsum[wid - 1] : 0);
    *total = wsum[31];
    return excl;
}

__global__ __launch_bounds__(1024) void scanscatter_kernel(const int* __restrict__ rows,
                                                           const int* __restrict__ cols,
                                                           const float* __restrict__ vals) {
    const int gtid = blockIdx.x * 1024 + threadIdx.x;
    int c = (gtid < V_) ? d_counts[gtid] : 0;
    int total;
    int excl = block_exscan(c, &total);
    __shared__ int s_off;
    if (threadIdx.x == 0) {
        s_off = 0;
        __threadfence();
        atomicExch(&d_agg[blockIdx.x], total + 1);
    }
    __syncthreads();
    if ((int)threadIdx.x < (int)blockIdx.x) {
        int v;
        do { v = atomicAdd(&d_agg[threadIdx.x], 0); } while (v == 0);
        atomicAdd(&s_off, v - 1);
    }
    __syncthreads();
    const int off = s_off;
    if (gtid < V_) {
        int r = excl + off;
        d_rowptr[gtid] = r;
        d_cursor[gtid] = r;
    }
    if (gtid == 0) d_rowptr[V_] = E_;

    // grid barrier: rowptr/cursor visible everywhere before scatter
    __threadfence();
    __syncthreads();
    if (threadIdx.x == 0) {
        unsigned t = atomicAdd(&s_count, 1);
        if (t == SCAN_B - 1) {
            s_count = 0;
            __threadfence();
            *(unsigned*)&s_phase = 1;
        } else {
            while (s_phase < 1) { }
            __threadfence();
        }
    }
    __syncthreads();

    const int stride = SCAN_B * 1024;
    for (int i = gtid; i < V_; i += stride) d_counts[i] = 0;
    if (gtid < SCAN_B) d_agg[gtid] = 0;
    for (int e = gtid; e < E_; e += stride) {
        int r = rows[e];
        int p = atomicAdd(&d_cursor[r], 1);
        d_ccol[p] = cols[e];
        d_cval[p] = vals[e];
    }
}

// ---------------- 3. SpMM pass 1 + transpose (per batch-half) ----------------
__global__ __launch_bounds__(256) void spmm1t_kernel(const float* __restrict__ in, int h,
                                                     float* __restrict__ x0T,
                                                     float* __restrict__ x1g) {
    __shared__ float st[8][336];
    const int wrp = threadIdx.x >> 5;
    const int lane = threadIdx.x & 31;
    const int v = blockIdx.x * 8 + wrp;
    const int bl = lane >> 3;
    const int f0 = (lane & 7) * 4;
    const float* base = in + ((size_t)(h * 4 + bl) * V_) * FIN_ + f0;

    const int s = __ldg(&d_rowptr[v]);
    const int e = __ldg(&d_rowptr[v + 1]);

    float4 aA = make_float4(0.f, 0.f, 0.f, 0.f);
    float4 aB = make_float4(0.f, 0.f, 0.f, 0.f);
    int i = s;
    for (; i + 1 < e; i += 2) {
        int   c0 = __ldg(&d_ccol[i]);
        int   c1 = __ldg(&d_ccol[i + 1]);
        float w0 = __ldg(&d_cval[i]);
        float w1 = __ldg(&d_cval[i + 1]);
        float4 u = __ldg(reinterpret_cast<const float4*>(base + (size_t)c0 * FIN_));
        float4 q = __ldg(reinterpret_cast<const float4*>(base + (size_t)c1 * FIN_));
        aA.x = fmaf(w0, u.x, aA.x); aA.y = fmaf(w0, u.y, aA.y);
        aA.z = fmaf(w0, u.z, aA.z); aA.w = fmaf(w0, u.w, aA.w);
        aB.x = fmaf(w1, q.x, aB.x); aB.y = fmaf(w1, q.y, aB.y);
        aB.z = fmaf(w1, q.z, aB.z); aB.w = fmaf(w1, q.w, aB.w);
    }
    if (i < e) {
        int   c0 = __ldg(&d_ccol[i]);
        float w0 = __ldg(&d_cval[i]);
        float4 u = __ldg(reinterpret_cast<const float4*>(base + (size_t)c0 * FIN_));
        aA.x = fmaf(w0, u.x, aA.x); aA.y = fmaf(w0, u.y, aA.y);
        aA.z = fmaf(w0, u.z, aA.z); aA.w = fmaf(w0, u.w, aA.w);
    }
    aA.x += aB.x; aA.y += aB.y; aA.z += aB.z; aA.w += aB.w;

    float4 o0 = __ldg(reinterpret_cast<const float4*>(base + (size_t)v * FIN_));

    float* s1 = st[wrp];
    float* s0 = st[wrp] + 168;
    s1[(f0 + 0) * 5 + bl] = aA.x; s1[(f0 + 1) * 5 + bl] = aA.y;
    s1[(f0 + 2) * 5 + bl] = aA.z; s1[(f0 + 3) * 5 + bl] = aA.w;
    s0[(f0 + 0) * 5 + bl] = o0.x; s0[(f0 + 1) * 5 + bl] = o0.y;
    s0[(f0 + 2) * 5 + bl] = o0.z; s0[(f0 + 3) * 5 + bl] = o0.w;
    __syncwarp();

    float4 r1, r0;
    r1.x = s1[5 * lane + 0]; r1.y = s1[5 * lane + 1];
    r1.z = s1[5 * lane + 2]; r1.w = s1[5 * lane + 3];
    r0.x = s0[5 * lane + 0]; r0.y = s0[5 * lane + 1];
    r0.z = s0[5 * lane + 2]; r0.w = s0[5 * lane + 3];

    *reinterpret_cast<float4*>(&x1g[(size_t)v * FH + lane * 4]) = r1;
    *reinterpret_cast<float4*>(&x0T[(size_t)v * FH + lane * 4]) = r0;
}

// ---------------- 4. SpMM passes 2/3 (interleaved layout): y = 2*(L x) - z ----------
__global__ __launch_bounds__(256) void spmm2_kernel(const float* __restrict__ x,
                                                    const float* __restrict__ z,
                                                    float* __restrict__ y) {
    const int wrp = threadIdx.x >> 5;
    const int lane = threadIdx.x & 31;
    const int v = blockIdx.x * 8 + wrp;
    const int p = lane * 4;
    const int s = __ldg(&d_rowptr[v]);
    const int e = __ldg(&d_rowptr[v + 1]);

    float4 a0 = make_float4(0.f, 0.f, 0.f, 0.f);
    float4 a1 = make_float4(0.f, 0.f, 0.f, 0.f);
    int i = s;
    for (; i + 1 < e; i += 2) {
        int   c0 = __ldg(&d_ccol[i]);
        int   c1 = __ldg(&d_ccol[i + 1]);
        float w0 = __ldg(&d_cval[i]);
        float w1 = __ldg(&d_cval[i + 1]);
        float4 u = __ldg(reinterpret_cast<const float4*>(&x[(size_t)c0 * FH + p]));
        float4 q = __ldg(reinterpret_cast<const float4*>(&x[(size_t)c1 * FH + p]));
        a0.x = fmaf(w0, u.x, a0.x); a0.y = fmaf(w0, u.y, a0.y);
        a0.z = fmaf(w0, u.z, a0.z); a0.w = fmaf(w0, u.w, a0.w);
        a1.x = fmaf(w1, q.x, a1.x); a1.y = fmaf(w1, q.y, a1.y);
        a1.z = fmaf(w1, q.z, a1.z); a1.w = fmaf(w1, q.w, a1.w);
    }
    if (i < e) {
        int   c0 = __ldg(&d_ccol[i]);
        float w0 = __ldg(&d_cval[i]);
        float4 u = __ldg(reinterpret_cast<const float4*>(&x[(size_t)c0 * FH + p]));
        a0.x = fmaf(w0, u.x, a0.x); a0.y = fmaf(w0, u.y, a0.y);
        a0.z = fmaf(w0, u.z, a0.z); a0.w = fmaf(w0, u.w, a0.w);
    }
    float4 zv = __ldg(reinterpret_cast<const float4*>(&z[(size_t)v * FH + p]));
    float4 r;
    r.x = 2.f * (a0.x + a1.x) - zv.x;
    r.y = 2.f * (a0.y + a1.y) - zv.y;
    r.z = 2.f * (a0.z + a1.z) - zv.z;
    r.w = 2.f * (a0.w + a1.w) - zv.w;
    *reinterpret_cast<float4*>(&y[(size_t)v * FH + p]) = r;
}

// ---------------- 5. einsum: warp owns 4 vertices; k-streamed smem staging ----------
// smem: ws 32KB + xst 16KB (one Chebyshev order at a time) = 48KB -> 4 blocks/SM.
// k outer loop; accumulators carried across k; __syncwarp fences around restaging.
__global__ __launch_bounds__(256) void einsum_kernel(const float* __restrict__ w,
                                                     const float* __restrict__ bias,
                                                     float* __restrict__ out, int h,
                                                     const float* __restrict__ xb4) {
    extern __shared__ __align__(16) float sm[];
    float*  ws  = sm;                                   // 8192 floats (32KB)
    float4* xst = reinterpret_cast<float4*>(sm + 8192); // 8 warps * 128 float4 (16KB)

    const int t = threadIdx.x;
    #pragma unroll
    for (int i = 0; i < 32; i++) ws[i * 256 + t] = w[i * 256 + t];
    __syncthreads();

    const int wrp = t >> 5;
    const int lane = t & 31;
    const int v0 = blockIdx.x * 32 + wrp * 4;           // 3125 blocks * 32 v = V_
    float4* xw = xst + wrp * 128;                       // this warp's slice: [j][q]

    const float bo0 = __ldg(&bias[lane]);
    const float bo1 = __ldg(&bias[lane + 32]);

    unsigned long long a[4][2][2];                      // [vertex j][o-slot][batch pair]
    #pragma unroll
    for (int j = 0; j < 4; j++)
        #pragma unroll
        for (int s2 = 0; s2 < 2; s2++) { a[j][s2][0] = 0ull; a[j][s2][1] = 0ull; }

    #pragma unroll
    for (int k = 0; k < K_; k++) {
        // stage order k: 4 vertices x 32 float4
        #pragma unroll
        for (int i = 0; i < 4; i++) {
            int idx = i * 32 + lane;                    // 0..127, j = idx>>5, q = idx&31
            xw[idx] = __ldg(reinterpret_cast<const float4*>(
                xb4 + (size_t)k * HVF + (size_t)(v0 + (idx >> 5)) * FH + (idx & 31) * 4));
        }
        __syncwarp();

        #pragma unroll 4
        for (int f = 0; f < FIN_; f++) {
            float w0 = ws[f * 256 + k * 64 + lane];
            float w1 = ws[f * 256 + k * 64 + 32 + lane];
            unsigned long long wp0 = pack2(w0, w0);
            unsigned long long wp1 = pack2(w1, w1);
            #pragma unroll
            for (int j = 0; j < 4; j++) {
                ulonglong2 xv = *reinterpret_cast<const ulonglong2*>(
                    &xw[j * 32 + f]);                   // broadcast LDS.128
                a[j][0][0] = fma2(xv.x, wp0, a[j][0][0]);
                a[j][0][1] = fma2(xv.y, wp0, a[j][0][1]);
                a[j][1][0] = fma2(xv.x, wp1, a[j][1][0]);
                a[j][1][1] = fma2(xv.y, wp1, a[j][1][1]);
            }
        }
        __syncwarp();                                   // done reading before restage
    }

    #pragma unroll
    for (int j = 0; j < 4; j++) {
        const int v = v0 + j;
        #pragma unroll
        for (int s2 = 0; s2 < 2; s2++) {
            float b0, b1, b2, b3;
            unpack2(a[j][s2][0], b0, b1);
            unpack2(a[j][s2][1], b2, b3);
            const int o = lane + s2 * 32;
            const float bb = s2 ? bo1 : bo0;
            out[((size_t)(h * 4 + 0) * V_ + v) * FOUT_ + o] = b0 + bb;
            out[((size_t)(h * 4 + 1) * V_ + v) * FOUT_ + o] = b1 + bb;
            out[((size_t)(h * 4 + 2) * V_ + v) * FOUT_ + o] = b2 + bb;
            out[((size_t)(h * 4 + 3) * V_ + v) * FOUT_ + o] = b3 + bb;
        }
    }
}

// ---------------- launch ----------------
extern "C" void kernel_launch(void* const* d_in, const int* in_sizes, int n_in,
                              void* d_out, int out_size) {
    const float* inputs = (const float*)d_in[0];
    const int*   rows   = (const int*)d_in[1];
    const int*   cols   = (const int*)d_in[2];
    const float* vals   = (const float*)d_in[3];
    const float* weight = (const float*)d_in[4];
    const float* bias   = (const float*)d_in[5];
    float* out = (float*)d_out;

    float* xbase;
    cudaGetSymbolAddress((void**)&xbase, d_x);

    // one-time config (first call is the uncaptured correctness run)
    static cudaStream_t s2 = nullptr;
    static cudaEvent_t evF = nullptr, evJ = nullptr;
    if (s2 == nullptr) {
        cudaFuncSetAttribute(einsum_kernel,
                             cudaFuncAttributeMaxDynamicSharedMemorySize, ESMEM);
        cudaStreamCreateWithFlags(&s2, cudaStreamNonBlocking);
        cudaEventCreateWithFlags(&evF, cudaEventDisableTiming);
        cudaEventCreateWithFlags(&evJ, cudaEventDisableTiming);
    }

    hist_kernel<<<(E_ + 255) / 256, 256>>>(rows);                   // default stream
    scanscatter_kernel<<<SCAN_B, 1024>>>(rows, cols, vals);         // default stream

    // fork: chain h=1 runs on s2, concurrent with chain h=0 on the default stream
    cudaEventRecord(evF, 0);
    cudaStreamWaitEvent(s2, evF, 0);

    for (int h = 0; h < 2; h++) {
        cudaStream_t st = (h == 0) ? (cudaStream_t)0 : s2;
        float* x0T = xbase + (size_t)h * 4 * HVF;
        float* x1  = x0T + HVF;
        float* x2  = x0T + 2 * HVF;
        float* x3  = x0T + 3 * HVF;
        spmm1t_kernel<<<V_ / 8, 256, 0, st>>>(inputs, h, x0T, x1);
        spmm2_kernel<<<V_ / 8, 256, 0, st>>>(x1, x0T, x2);
        spmm2_kernel<<<V_ / 8, 256, 0, st>>>(x2, x1, x3);
        einsum_kernel<<<V_ / 32, 256, ESMEM, st>>>(weight, bias, out, h, x0T);
    }

    // join: default stream waits for chain h=1
    cudaEventRecord(evJ, s2);
    cudaStreamWaitEvent((cudaStream_t)0, evJ, 0);
}